// round 3
// baseline (speedup 1.0000x reference)
#include <cuda_runtime.h>
#include <math.h>

// Problem constants
#define B_  32
#define T_  256
#define D_  1024
#define M_  256
#define S_  64
#define ROWS_ (B_*S_)     // 2048
#define BT_  (B_*T_)      // 8192

// ---------------- scratch (static device globals; no allocation) ----------------
// g_mv: [BT, 512] : cols [0,256) = mem_input (x@Wi.T+bi), cols [256,512) = vals (x@Wv.T+bv)
__device__ float g_mv[(size_t)BT_ * 512];
// g_vproj: [BT, 768] : vals @ {Wr_x,Wz_x,Wu_x}.T + {br,bz,bu}  (gate-major: 0..255 r, 256..511 z, 512..767 u)
__device__ float g_vproj[(size_t)BT_ * 768];
// per-step intermediates
__device__ float g_rm[(size_t)ROWS_ * M_];   // r * mem
__device__ float g_zg[(size_t)ROWS_ * M_];   // z gate
__device__ float g_ww[ROWS_];                // write weights (softmax)
__device__ float g_usage[ROWS_];             // usage state
// packed weights
__device__ float g_Wiv[(size_t)512 * D_];    // rows 0..255 Wi, 256..511 Wv   [512,1024]
__device__ float g_biv[512];
__device__ float g_Wx[(size_t)768 * M_];     // x-halves of Wr,Wz,Wu  [768,256]
__device__ float g_Wh[(size_t)768 * M_];     // h-halves of Wr,Wz,Wu  [768,256]
__device__ float g_bx[768];

// ---------------- pack kernel ----------------
__global__ void k_pack(const float* __restrict__ Wi, const float* __restrict__ bi,
                       const float* __restrict__ Wv, const float* __restrict__ bv,
                       const float* __restrict__ Wr, const float* __restrict__ br,
                       const float* __restrict__ Wz, const float* __restrict__ bz,
                       const float* __restrict__ Wu, const float* __restrict__ bu)
{
    int idx = blockIdx.x * blockDim.x + threadIdx.x;   // grid covers 524288
    if (idx < 512 * 1024) {
        int r = idx >> 10, k = idx & 1023;
        g_Wiv[idx] = (r < 256) ? Wi[r * 1024 + k] : Wv[(r - 256) * 1024 + k];
    }
    if (idx < 768 * 256) {
        int n = idx >> 8, k = idx & 255;
        int gate = n >> 8, j = n & 255;
        const float* Wg = (gate == 0) ? Wr : ((gate == 1) ? Wz : Wu);
        g_Wx[idx] = Wg[j * 512 + k];
        g_Wh[idx] = Wg[j * 512 + 256 + k];
    }
    if (idx < 768) {
        g_bx[idx] = (idx < 256) ? br[idx] : ((idx < 512) ? bz[idx - 256] : bu[idx - 512]);
    }
    if (idx < 512) {
        g_biv[idx] = (idx < 256) ? bi[idx] : bv[idx - 256];
    }
}

// ---------------- shared 64x64x16 fp32 GEMM tile core ----------------
// acc[i][j] += sum_k A[row0+ty*4+i][k] * W[n0+tx*4+j][k]   (both operands K-major)
template<int KTILE>
__device__ __forceinline__ void gemm_tile(const float* __restrict__ A, int lda,
                                          const float* __restrict__ W, int ldw,
                                          int K, int row0, int n0, float acc[4][4])
{
    __shared__ float sA[KTILE][68];
    __shared__ float sW[KTILE][68];
    const int tid = threadIdx.x;
    const int lr = tid >> 2;            // 0..63
    const int lk = (tid & 3) * 4;       // 0,4,8,12
    const int ty = tid >> 4;            // 0..15
    const int tx = tid & 15;            // 0..15
    for (int k0 = 0; k0 < K; k0 += KTILE) {
        float4 av = *(const float4*)(A + (size_t)(row0 + lr) * lda + k0 + lk);
        float4 wv = *(const float4*)(W + (size_t)(n0 + lr) * ldw + k0 + lk);
        __syncthreads();
        sA[lk + 0][lr] = av.x; sA[lk + 1][lr] = av.y; sA[lk + 2][lr] = av.z; sA[lk + 3][lr] = av.w;
        sW[lk + 0][lr] = wv.x; sW[lk + 1][lr] = wv.y; sW[lk + 2][lr] = wv.z; sW[lk + 3][lr] = wv.w;
        __syncthreads();
        #pragma unroll
        for (int kk = 0; kk < KTILE; kk++) {
            float4 a = *(const float4*)&sA[kk][ty * 4];
            float4 w = *(const float4*)&sW[kk][tx * 4];
            float ar[4] = {a.x, a.y, a.z, a.w};
            float wr[4] = {w.x, w.y, w.z, w.w};
            #pragma unroll
            for (int i = 0; i < 4; i++)
                #pragma unroll
                for (int j = 0; j < 4; j++)
                    acc[i][j] = fmaf(ar[i], wr[j], acc[i][j]);
        }
    }
}

// ---------------- precompute GEMMs ----------------
// mode 0: g_mv[8192,512]   = hidden[8192,1024] @ g_Wiv.T + g_biv
// mode 1: g_vproj[8192,768] = vals[8192,256]    @ g_Wx.T  + g_bx
__global__ void k_gemm_pre(const float* __restrict__ hidden, int mode)
{
    const float* A; const float* W; const float* bias; float* C;
    int lda, ldw, ldc, K, ntn;
    if (mode == 0) { A = hidden;     lda = 1024; W = g_Wiv; ldw = 1024; bias = g_biv; C = g_mv;    ldc = 512; K = 1024; ntn = 8;  }
    else           { A = g_mv + 256; lda = 512;  W = g_Wx;  ldw = 256;  bias = g_bx;  C = g_vproj; ldc = 768; K = 256;  ntn = 12; }
    int tr = blockIdx.x / ntn, tc = blockIdx.x % ntn;
    int row0 = tr * 64, n0 = tc * 64;
    float acc[4][4] = {};
    gemm_tile<16>(A, lda, W, ldw, K, row0, n0, acc);
    int ty = threadIdx.x >> 4, tx = threadIdx.x & 15;
    #pragma unroll
    for (int i = 0; i < 4; i++) {
        int r = row0 + ty * 4 + i;
        #pragma unroll
        for (int j = 0; j < 4; j++) {
            int n = n0 + tx * 4 + j;
            C[(size_t)r * ldc + n] = acc[i][j] + bias[n];
        }
    }
}

// ---------------- per-step kernel A: sim+softmax (blocks 0..31) + r,z GEMM (blocks 32..287) ----------------
__global__ void k_step_a(const float* __restrict__ mem, int t)
{
    if (blockIdx.x < B_) {
        __shared__ float dvec[M_];
        __shared__ float sc[S_];
        int b = blockIdx.x;
        int tid = threadIdx.x, lane = tid & 31, warp = tid >> 5;
        dvec[tid] = g_mv[(size_t)(b * T_ + t) * 512 + tid];   // mem_input row
        __syncthreads();
        #pragma unroll
        for (int si = 0; si < 8; si++) {
            int s = warp * 8 + si;
            const float* mr = mem + (size_t)(b * S_ + s) * M_;
            float p = 0.f;
            for (int k = lane; k < M_; k += 32) p += dvec[k] * mr[k];
            #pragma unroll
            for (int off = 16; off; off >>= 1) p += __shfl_xor_sync(0xffffffffu, p, off);
            if (lane == 0) sc[s] = -p + 0.2f * g_usage[b * S_ + s];   // age term cancels in softmax
        }
        __syncthreads();
        if (tid < 32) {
            float x0 = sc[tid], x1 = sc[tid + 32];
            float mx = fmaxf(x0, x1);
            #pragma unroll
            for (int off = 16; off; off >>= 1) mx = fmaxf(mx, __shfl_xor_sync(0xffffffffu, mx, off));
            float e0 = expf(x0 - mx), e1 = expf(x1 - mx);
            float s = e0 + e1;
            #pragma unroll
            for (int off = 16; off; off >>= 1) s += __shfl_xor_sync(0xffffffffu, s, off);
            float inv = 1.f / s;
            g_ww[b * S_ + tid]      = e0 * inv;
            g_ww[b * S_ + tid + 32] = e1 * inv;
        }
    } else {
        int bx = blockIdx.x - B_;
        int tr = bx >> 3, tc = bx & 7;        // rows 2048/64=32 tiles, cols 512/64=8 tiles
        int row0 = tr * 64, n0 = tc * 64;
        float acc[4][4] = {};
        gemm_tile<16>(mem, M_, g_Wh, M_, M_, row0, n0, acc);
        int b = row0 >> 6;
        const float* vp = g_vproj + (size_t)(b * T_ + t) * 768;
        int ty = threadIdx.x >> 4, tx = threadIdx.x & 15;
        #pragma unroll
        for (int i = 0; i < 4; i++) {
            int r = row0 + ty * 4 + i;
            #pragma unroll
            for (int j = 0; j < 4; j++) {
                int n = n0 + tx * 4 + j;
                float v = 1.f / (1.f + expf(-(acc[i][j] + vp[n])));   // sigmoid
                if (n < 256) g_rm[(size_t)r * M_ + n] = v * mem[(size_t)r * M_ + n];   // r * mem
                else         g_zg[(size_t)r * M_ + (n - 256)] = v;                     // z
            }
        }
    }
}

// ---------------- per-step kernel B: cand GEMM + gated blend (pre-normalization) ----------------
__global__ void k_step_b(float* __restrict__ mem, int t)
{
    int tr = blockIdx.x >> 2, tc = blockIdx.x & 3;   // 32 x 4 tiles
    int row0 = tr * 64, n0 = tc * 64;
    float acc[4][4] = {};
    gemm_tile<16>(g_rm, M_, g_Wh + 512 * M_, M_, M_, row0, n0, acc);
    int b = row0 >> 6;
    const float* vp = g_vproj + (size_t)(b * T_ + t) * 768 + 512;
    int ty = threadIdx.x >> 4, tx = threadIdx.x & 15;
    #pragma unroll
    for (int i = 0; i < 4; i++) {
        int r = row0 + ty * 4 + i;
        float ww = g_ww[r];
        float w = ww * 0.5f;                 // UPDATE_RATE
        bool upd = (ww > 0.01f);
        #pragma unroll
        for (int j = 0; j < 4; j++) {
            int n = n0 + tx * 4 + j;
            float cand = tanhf(acc[i][j] + vp[n]);
            float z = g_zg[(size_t)r * M_ + n];
            float m = mem[(size_t)r * M_ + n];
            float nh = (1.f - z) * m + z * cand;
            float out = upd ? (m * (1.f - w) + nh * w) : m;
            mem[(size_t)r * M_ + n] = out;
        }
    }
}

// ---------------- per-step kernel N: row L2-renormalize + usage update ----------------
__global__ void k_norm(float* __restrict__ mem, int upd)
{
    int row = blockIdx.x, tid = threadIdx.x;
    float v = mem[(size_t)row * M_ + tid];
    float ss = v * v;
    #pragma unroll
    for (int off = 16; off; off >>= 1) ss += __shfl_xor_sync(0xffffffffu, ss, off);
    __shared__ float wsum[8];
    if ((tid & 31) == 0) wsum[tid >> 5] = ss;
    __syncthreads();
    float tot = wsum[0] + wsum[1] + wsum[2] + wsum[3] + wsum[4] + wsum[5] + wsum[6] + wsum[7];
    float scale = 1.f / fmaxf(sqrtf(tot), 1e-12f);
    mem[(size_t)row * M_ + tid] = v * scale;
    if (tid == 0 && upd) {
        float ww = g_ww[row];
        g_usage[row] = (g_usage[row] + (ww > 0.01f ? ww : 0.f)) * 0.99f;
    }
}

// ---------------- init: mem0 = normalize(0.01 * memory_init), usage = 0 ----------------
__global__ void k_init(const float* __restrict__ mi, float* __restrict__ mem)
{
    int row = blockIdx.x, tid = threadIdx.x;
    float v = 0.01f * mi[(size_t)row * M_ + tid];
    float ss = v * v;
    #pragma unroll
    for (int off = 16; off; off >>= 1) ss += __shfl_xor_sync(0xffffffffu, ss, off);
    __shared__ float wsum[8];
    if ((tid & 31) == 0) wsum[tid >> 5] = ss;
    __syncthreads();
    float tot = wsum[0] + wsum[1] + wsum[2] + wsum[3] + wsum[4] + wsum[5] + wsum[6] + wsum[7];
    float scale = 1.f / fmaxf(sqrtf(tot), 1e-12f);
    mem[(size_t)row * M_ + tid] = v * scale;
    if (tid == 0) { g_usage[row] = 0.f; g_ww[row] = 0.f; }
}

// ---------------- launch ----------------
extern "C" void kernel_launch(void* const* d_in, const int* in_sizes, int n_in,
                              void* d_out, int out_size)
{
    const float* hidden  = (const float*)d_in[0];
    const float* meminit = (const float*)d_in[1];
    const float* Wi = (const float*)d_in[2];
    const float* bi = (const float*)d_in[3];
    const float* Wv = (const float*)d_in[4];
    const float* bv = (const float*)d_in[5];
    const float* Wr = (const float*)d_in[6];
    const float* br = (const float*)d_in[7];
    const float* Wz = (const float*)d_in[8];
    const float* bz = (const float*)d_in[9];
    const float* Wu = (const float*)d_in[10];
    const float* bu = (const float*)d_in[11];
    float* mem = (float*)d_out;   // d_out doubles as the live memory state [B,S,M]

    k_pack<<<2048, 256>>>(Wi, bi, Wv, bv, Wr, br, Wz, bz, Wu, bu);
    k_init<<<ROWS_, 256>>>(meminit, mem);
    k_gemm_pre<<<128 * 8, 256>>>(hidden, 0);    // mem_input | vals
    k_gemm_pre<<<128 * 12, 256>>>(hidden, 1);   // VR | VZ | VU

    for (int t = 0; t < T_; t++) {
        k_step_a<<<B_ + 256, 256>>>(mem, t);    // sim/softmax + r,z
        k_step_b<<<128, 256>>>(mem, t);         // cand + gated blend
        k_norm<<<ROWS_, 256>>>(mem, 1);         // renormalize + usage
    }
}

// round 10
// speedup vs baseline: 1.1384x; 1.1384x over previous
#include <cuda_runtime.h>
#include <math.h>

#define B_  32
#define T_  256
#define D_  1024
#define M_  256
#define S_  64
#define ROWS_ 2048
#define BT_  8192

// ---------------- static device scratch ----------------
__device__ float g_mem[(size_t)ROWS_ * M_];      // raw (pre-norm) memory, updated in place
__device__ float g_ss[B_ * 4 * S_];              // sum-of-squares partials [b][j4][s]
__device__ float g_scl[B_ * S_];                 // per-row norm scale (written by step1)
__device__ float g_usage[ROWS_];
__device__ float g_ww[ROWS_];
__device__ int   g_act[B_ * S_];                 // active row list per batch
__device__ int   g_cnt[B_];
__device__ float g_rm[(size_t)ROWS_ * M_];       // r * mem_norm, compressed rows per batch
__device__ float g_zg[(size_t)ROWS_ * M_];       // z gate, compressed rows per batch
__device__ float g_mv[(size_t)BT_ * 512];        // mem_input | vals
__device__ float g_vproj[(size_t)BT_ * 768];     // vals @ {Wr,Wz,Wu}_x^T + biases
__device__ float g_Wiv[(size_t)512 * D_];
__device__ float g_biv[512];
__device__ float g_Wx[(size_t)768 * M_];         // x-halves
__device__ float g_Wh[(size_t)768 * M_];         // h-halves [n][k], n = gate*256+j
__device__ float g_bx[768];

__device__ __forceinline__ float sigm(float x) { return 1.f / (1.f + expf(-x)); }

// ---------------- pack ----------------
__global__ void k_pack(const float* __restrict__ Wi, const float* __restrict__ bi,
                       const float* __restrict__ Wv, const float* __restrict__ bv,
                       const float* __restrict__ Wr, const float* __restrict__ br,
                       const float* __restrict__ Wz, const float* __restrict__ bz,
                       const float* __restrict__ Wu, const float* __restrict__ bu)
{
    int idx = blockIdx.x * blockDim.x + threadIdx.x;
    if (idx < 512 * 1024) {
        int r = idx >> 10, k = idx & 1023;
        g_Wiv[idx] = (r < 256) ? Wi[r * 1024 + k] : Wv[(r - 256) * 1024 + k];
    }
    if (idx < 768 * 256) {
        int n = idx >> 8, k = idx & 255;
        int gate = n >> 8, jj = n & 255;
        const float* Wg = (gate == 0) ? Wr : ((gate == 1) ? Wz : Wu);
        g_Wx[idx] = Wg[jj * 512 + k];
        g_Wh[idx] = Wg[jj * 512 + 256 + k];
    }
    if (idx < 768) g_bx[idx] = (idx < 256) ? br[idx] : ((idx < 512) ? bz[idx - 256] : bu[idx - 512]);
    if (idx < 512) g_biv[idx] = (idx < 256) ? bi[idx] : bv[idx - 256];
}

// ---------------- init: raw = 0.01*mi, ss partials, usage = 0 ----------------
__global__ void k_init(const float* __restrict__ mi)
{
    int row = blockIdx.x, tid = threadIdx.x;
    float v = 0.01f * mi[(size_t)row * M_ + tid];
    g_mem[(size_t)row * M_ + tid] = v;
    float ss = v * v;
    #pragma unroll
    for (int off = 16; off; off >>= 1) ss += __shfl_xor_sync(0xffffffffu, ss, off);
    __shared__ float wsum[8];
    if ((tid & 31) == 0) wsum[tid >> 5] = ss;
    __syncthreads();
    if (tid < 4) {
        int b = row >> 6, s = row & 63;
        g_ss[(b * 4 + tid) * 64 + s] = wsum[2 * tid] + wsum[2 * tid + 1];
    }
    if (tid == 0) g_usage[row] = 0.f;
}

// ---------------- precompute GEMMs ----------------
template<int KTILE>
__device__ __forceinline__ void gemm_tile(const float* __restrict__ A, int lda,
                                          const float* __restrict__ W, int ldw,
                                          int K, int row0, int n0, float acc[4][4])
{
    __shared__ __align__(16) float sA[KTILE][68];
    __shared__ __align__(16) float sW[KTILE][68];
    const int tid = threadIdx.x;
    const int lr = tid >> 2, lk = (tid & 3) * 4;
    const int ty = tid >> 4, tx = tid & 15;
    for (int k0 = 0; k0 < K; k0 += KTILE) {
        float4 av = *(const float4*)(A + (size_t)(row0 + lr) * lda + k0 + lk);
        float4 wv = *(const float4*)(W + (size_t)(n0 + lr) * ldw + k0 + lk);
        __syncthreads();
        sA[lk + 0][lr] = av.x; sA[lk + 1][lr] = av.y; sA[lk + 2][lr] = av.z; sA[lk + 3][lr] = av.w;
        sW[lk + 0][lr] = wv.x; sW[lk + 1][lr] = wv.y; sW[lk + 2][lr] = wv.z; sW[lk + 3][lr] = wv.w;
        __syncthreads();
        #pragma unroll
        for (int kk = 0; kk < KTILE; kk++) {
            float4 a = *(const float4*)&sA[kk][ty * 4];
            float4 w = *(const float4*)&sW[kk][tx * 4];
            float ar[4] = {a.x, a.y, a.z, a.w};
            float wr[4] = {w.x, w.y, w.z, w.w};
            #pragma unroll
            for (int i = 0; i < 4; i++)
                #pragma unroll
                for (int j = 0; j < 4; j++)
                    acc[i][j] = fmaf(ar[i], wr[j], acc[i][j]);
        }
    }
}

__global__ void k_gemm_pre(const float* __restrict__ hidden, int mode)
{
    const float* A; const float* W; const float* bias; float* C;
    int lda, ldw, ldc, K, ntn;
    if (mode == 0) { A = hidden;     lda = 1024; W = g_Wiv; ldw = 1024; bias = g_biv; C = g_mv;    ldc = 512; K = 1024; ntn = 8;  }
    else           { A = g_mv + 256; lda = 512;  W = g_Wx;  ldw = 256;  bias = g_bx;  C = g_vproj; ldc = 768; K = 256;  ntn = 12; }
    int tr = blockIdx.x / ntn, tc = blockIdx.x % ntn;
    int row0 = tr * 64, n0 = tc * 64;
    float acc[4][4] = {};
    gemm_tile<16>(A, lda, W, ldw, K, row0, n0, acc);
    int ty = threadIdx.x >> 4, tx = threadIdx.x & 15;
    #pragma unroll
    for (int i = 0; i < 4; i++) {
        int r = row0 + ty * 4 + i;
        #pragma unroll
        for (int j = 0; j < 4; j++) {
            int n = n0 + tx * 4 + j;
            C[(size_t)r * ldc + n] = acc[i][j] + bias[n];
        }
    }
}

// ---------------- step1: scale + sim + softmax + usage + active-list (grid 32) ----------------
__global__ void __launch_bounds__(256) k_step1(int t)
{
    __shared__ __align__(16) float dvec[256];
    __shared__ float sScl_[64], sSco[64], sWw_[64];
    int b = blockIdx.x;
    int tid = threadIdx.x, lane = tid & 31, warp = tid >> 5;

    if (tid < 64) {
        const float* ssB = g_ss + b * 256;
        float tot = ssB[tid] + ssB[64 + tid] + ssB[128 + tid] + ssB[192 + tid];
        float sc = 1.f / fmaxf(sqrtf(tot), 1e-12f);
        sScl_[tid] = sc;
        g_scl[b * 64 + tid] = sc;
    }
    dvec[tid] = g_mv[(size_t)(b * T_ + t) * 512 + tid];
    __syncthreads();

    // sim over 8 rows per warp (raw dot; scale folded into score)
    #pragma unroll
    for (int rr = 0; rr < 8; rr++) {
        int s = warp * 8 + rr;
        const float* mr = g_mem + (size_t)(b * 64 + s) * M_ + lane * 8;
        float4 m0 = *(const float4*)mr, m1 = *(const float4*)(mr + 4);
        float4 q0 = *(const float4*)&dvec[lane * 8], q1 = *(const float4*)&dvec[lane * 8 + 4];
        float p = m0.x * q0.x;
        p = fmaf(m0.y, q0.y, p); p = fmaf(m0.z, q0.z, p); p = fmaf(m0.w, q0.w, p);
        p = fmaf(m1.x, q1.x, p); p = fmaf(m1.y, q1.y, p);
        p = fmaf(m1.z, q1.z, p); p = fmaf(m1.w, q1.w, p);
        #pragma unroll
        for (int off = 16; off; off >>= 1) p += __shfl_xor_sync(0xffffffffu, p, off);
        if (lane == 0) sSco[s] = p;
    }
    __syncthreads();
    if (tid < 64) sSco[tid] = -sSco[tid] * sScl_[tid] + 0.2f * g_usage[b * 64 + tid];
    __syncthreads();
    if (tid < 32) {   // full warp 0: softmax over 64 scores
        float x0 = sSco[tid], x1 = sSco[tid + 32];
        float mx = fmaxf(x0, x1);
        #pragma unroll
        for (int off = 16; off; off >>= 1) mx = fmaxf(mx, __shfl_xor_sync(0xffffffffu, mx, off));
        float e0 = expf(x0 - mx), e1 = expf(x1 - mx);
        float ssum = e0 + e1;
        #pragma unroll
        for (int off = 16; off; off >>= 1) ssum += __shfl_xor_sync(0xffffffffu, ssum, off);
        float inv = 1.f / ssum;
        sWw_[tid] = e0 * inv; sWw_[tid + 32] = e1 * inv;
        g_ww[b * 64 + tid] = e0 * inv; g_ww[b * 64 + tid + 32] = e1 * inv;
    }
    __syncthreads();
    if (tid < 32) {   // full warp 0: compact active list
        bool a0 = sWw_[tid] > 0.01f, a1 = sWw_[tid + 32] > 0.01f;
        unsigned m0 = __ballot_sync(0xffffffffu, a0);
        unsigned m1 = __ballot_sync(0xffffffffu, a1);
        int c0 = __popc(m0);
        if (a0) g_act[b * 64 + __popc(m0 & ((1u << tid) - 1))] = tid;
        if (a1) g_act[b * 64 + c0 + __popc(m1 & ((1u << tid) - 1))] = tid + 32;
        if (tid == 0) g_cnt[b] = c0 + __popc(m1);
    }
    if (tid < 64) {
        float w_ = sWw_[tid];
        g_usage[b * 64 + tid] = (g_usage[b * 64 + tid] + (w_ > 0.01f ? w_ : 0.f)) * 0.99f;
    }
}

// ---------------- active-row GEMM tile ----------------
template<int KTILE, bool IND>
__device__ __forceinline__ void gemm_tile2(const float* __restrict__ A,   // batch base [64][256]
                                           const float* __restrict__ W,   // [n][256], n0 offset
                                           int n0, const int* __restrict__ sAct_,
                                           const float* __restrict__ sScl_, int cnt,
                                           float acc[4][4])
{
    __shared__ __align__(16) float sA[KTILE][68];
    __shared__ __align__(16) float sW[KTILE][68];
    const int tid = threadIdx.x;
    const int lr = tid >> 2, lk = (tid & 3) * 4;
    const int ty = tid >> 4, tx = tid & 15;
    const bool aval = lr < cnt;
    int arow = lr; float sc = 1.f;
    if (IND) { arow = aval ? sAct_[lr] : 0; sc = aval ? sScl_[arow] : 0.f; }
    const bool doC = (ty * 4) < cnt;   // whole 4-row microtile dead -> skip FMA (no syncs inside)
    for (int k0 = 0; k0 < 256; k0 += KTILE) {
        float4 av = make_float4(0.f, 0.f, 0.f, 0.f);
        if (aval) {
            av = *(const float4*)(A + (size_t)arow * 256 + k0 + lk);
            if (IND) { av.x *= sc; av.y *= sc; av.z *= sc; av.w *= sc; }
        }
        float4 wv = *(const float4*)(W + (size_t)(n0 + lr) * 256 + k0 + lk);
        __syncthreads();
        sA[lk + 0][lr] = av.x; sA[lk + 1][lr] = av.y; sA[lk + 2][lr] = av.z; sA[lk + 3][lr] = av.w;
        sW[lk + 0][lr] = wv.x; sW[lk + 1][lr] = wv.y; sW[lk + 2][lr] = wv.z; sW[lk + 3][lr] = wv.w;
        __syncthreads();
        if (doC) {
            #pragma unroll
            for (int kk = 0; kk < KTILE; kk++) {
                float4 a = *(const float4*)&sA[kk][ty * 4];
                float4 w = *(const float4*)&sW[kk][tx * 4];
                float ar[4] = {a.x, a.y, a.z, a.w};
                float wr[4] = {w.x, w.y, w.z, w.w};
                #pragma unroll
                for (int i = 0; i < 4; i++)
                    #pragma unroll
                    for (int j = 0; j < 4; j++)
                        acc[i][j] = fmaf(ar[i], wr[j], acc[i][j]);
            }
        }
    }
}

// ---------------- step2: r,z GEMM over active rows (grid 32*8) ----------------
__global__ void __launch_bounds__(256) k_step2(int t)
{
    int b = blockIdx.x >> 3, j = blockIdx.x & 7;
    __shared__ int sAct_[64]; __shared__ float sScl_[64]; __shared__ int sCnt_;
    int tid = threadIdx.x;
    if (tid < 64) { sAct_[tid] = g_act[b * 64 + tid]; sScl_[tid] = g_scl[b * 64 + tid]; }
    if (tid == 0) sCnt_ = g_cnt[b];
    __syncthreads();
    const int cnt = sCnt_;

    float acc[4][4] = {};
    gemm_tile2<16, true>(g_mem + (size_t)b * S_ * M_, g_Wh, j * 64, sAct_, sScl_, cnt, acc);

    int ty = tid >> 4, tx = tid & 15;
    float4 vp = __ldcg((const float4*)(g_vproj + (size_t)(b * T_ + t) * 768 + j * 64 + tx * 4));
    float vv[4] = {vp.x, vp.y, vp.z, vp.w};
    #pragma unroll
    for (int i = 0; i < 4; i++) {
        int arow = ty * 4 + i;
        if (arow >= cnt) continue;     // no sync primitives below
        int row = sAct_[arow];
        float4 o; float* op = (float*)&o;
        if (j < 4) {                    // r gate -> r * mem_norm
            float sc = sScl_[row];
            float4 m4 = __ldcg((const float4*)(g_mem + (size_t)(b * 64 + row) * 256 + j * 64 + tx * 4));
            float mm[4] = {m4.x * sc, m4.y * sc, m4.z * sc, m4.w * sc};
            #pragma unroll
            for (int q = 0; q < 4; q++) op[q] = sigm(acc[i][q] + vv[q]) * mm[q];
            __stcg((float4*)(g_rm + (size_t)(b * 64 + arow) * 256 + j * 64 + tx * 4), o);
        } else {                        // z gate
            #pragma unroll
            for (int q = 0; q < 4; q++) op[q] = sigm(acc[i][q] + vv[q]);
            __stcg((float4*)(g_zg + (size_t)(b * 64 + arow) * 256 + (j - 4) * 64 + tx * 4), o);
        }
    }
}

// ---------------- step3: cand GEMM + blend in place + ss partials (grid 32*4) ----------------
__global__ void __launch_bounds__(256) k_step3(int t)
{
    int b = blockIdx.x >> 2, j = blockIdx.x & 3;
    __shared__ int sAct_[64]; __shared__ float sScl_[64]; __shared__ int sCnt_;
    int tid = threadIdx.x;
    if (tid < 64) { sAct_[tid] = g_act[b * 64 + tid]; sScl_[tid] = g_scl[b * 64 + tid]; }
    if (tid == 0) sCnt_ = g_cnt[b];
    __syncthreads();
    const int cnt = sCnt_;

    float acc[4][4] = {};
    gemm_tile2<16, false>(g_rm + (size_t)b * S_ * M_, g_Wh + 512 * 256, j * 64, sAct_, sScl_, cnt, acc);

    int ty = tid >> 4, tx = tid & 15;
    float4 vp = __ldcg((const float4*)(g_vproj + (size_t)(b * T_ + t) * 768 + 512 + j * 64 + tx * 4));
    float vv[4] = {vp.x, vp.y, vp.z, vp.w};
    #pragma unroll
    for (int i = 0; i < 4; i++) {
        int arow = ty * 4 + i;
        bool ok = arow < cnt;
        int row = ok ? sAct_[arow] : 0;
        float ssum = 0.f;
        if (ok) {
            float sc = sScl_[row];
            float w_ = g_ww[b * 64 + row] * 0.5f;
            float4 z4 = __ldcg((const float4*)(g_zg + (size_t)(b * 64 + arow) * 256 + j * 64 + tx * 4));
            float4 m4 = __ldcg((const float4*)(g_mem + (size_t)(b * 64 + row) * 256 + j * 64 + tx * 4));
            float zz[4] = {z4.x, z4.y, z4.z, z4.w};
            float mm[4] = {m4.x * sc, m4.y * sc, m4.z * sc, m4.w * sc};
            float4 o; float* op = (float*)&o;
            #pragma unroll
            for (int q = 0; q < 4; q++) {
                float cand = tanhf(acc[i][q] + vv[q]);
                float nh = (1.f - zz[q]) * mm[q] + zz[q] * cand;
                float ov = mm[q] * (1.f - w_) + nh * w_;
                op[q] = ov; ssum = fmaf(ov, ov, ssum);
            }
            __stcg((float4*)(g_mem + (size_t)(b * 64 + row) * 256 + j * 64 + tx * 4), o);
        }
        // UNCONDITIONAL shuffles; xor<=8 keeps the two 16-lane tx groups independent
        ssum += __shfl_xor_sync(0xffffffffu, ssum, 1);
        ssum += __shfl_xor_sync(0xffffffffu, ssum, 2);
        ssum += __shfl_xor_sync(0xffffffffu, ssum, 4);
        ssum += __shfl_xor_sync(0xffffffffu, ssum, 8);
        if (ok && tx == 0) g_ss[(b * 4 + j) * 64 + row] = ssum;
    }
}

// ---------------- final normalize into d_out ----------------
__global__ void k_fin(float* __restrict__ out)
{
    int row = blockIdx.x, tid = threadIdx.x;
    __shared__ float sc;
    if (tid == 0) {
        int b = row >> 6, s = row & 63;
        const float* ssB = g_ss + b * 256;
        float tot = ssB[s] + ssB[64 + s] + ssB[128 + s] + ssB[192 + s];
        sc = 1.f / fmaxf(sqrtf(tot), 1e-12f);
    }
    __syncthreads();
    out[(size_t)row * M_ + tid] = g_mem[(size_t)row * M_ + tid] * sc;
}

// ---------------- launch ----------------
extern "C" void kernel_launch(void* const* d_in, const int* in_sizes, int n_in,
                              void* d_out, int out_size)
{
    const float* hidden  = (const float*)d_in[0];
    const float* meminit = (const float*)d_in[1];
    const float* Wi = (const float*)d_in[2];
    const float* bi = (const float*)d_in[3];
    const float* Wv = (const float*)d_in[4];
    const float* bv = (const float*)d_in[5];
    const float* Wr = (const float*)d_in[6];
    const float* br = (const float*)d_in[7];
    const float* Wz = (const float*)d_in[8];
    const float* bz = (const float*)d_in[9];
    const float* Wu = (const float*)d_in[10];
    const float* bu = (const float*)d_in[11];

    k_pack<<<2048, 256>>>(Wi, bi, Wv, bv, Wr, br, Wz, bz, Wu, bu);
    k_init<<<ROWS_, 256>>>(meminit);
    k_gemm_pre<<<128 * 8, 256>>>(hidden, 0);    // mem_input | vals
    k_gemm_pre<<<128 * 12, 256>>>(hidden, 1);   // VR | VZ | VU

    for (int t = 0; t < T_; t++) {
        k_step1<<<B_, 256>>>(t);
        k_step2<<<B_ * 8, 256>>>(t);
        k_step3<<<B_ * 4, 256>>>(t);
    }
    k_fin<<<ROWS_, 256>>>((float*)d_out);
}

// round 11
// speedup vs baseline: 1.3598x; 1.1945x over previous
#include <cuda_runtime.h>
#include <math.h>

#define B_  32
#define T_  256
#define D_  1024
#define M_  256
#define S_  64
#define ROWS_ 2048
#define BT_  8192

// ---------------- static device scratch ----------------
__device__ float g_mem[(size_t)ROWS_ * M_];      // raw (pre-norm) memory, updated in place
__device__ float g_ss[B_ * 4 * S_];              // sum-of-squares partials [b][j4][s]
__device__ float g_scl[B_ * S_];                 // per-row norm scale (published by step2 j==0)
__device__ float g_usage[2][ROWS_];              // parity double-buffered usage state
__device__ float g_ww[ROWS_];
__device__ int   g_act[B_ * S_];                 // active row list per batch
__device__ int   g_cnt[B_];
__device__ float g_rm[(size_t)ROWS_ * M_];       // r * mem_norm, compressed rows per batch
__device__ float g_zg[(size_t)ROWS_ * M_];       // z gate, compressed rows per batch
__device__ float g_mv[(size_t)BT_ * 512];        // mem_input | vals
__device__ float g_vproj[(size_t)BT_ * 768];     // vals @ {Wr,Wz,Wu}_x^T + biases
__device__ float g_Wiv[(size_t)512 * D_];
__device__ float g_biv[512];
__device__ float g_Wx[(size_t)768 * M_];         // x-halves
__device__ float g_Wh[(size_t)768 * M_];         // h-halves [n][k], n = gate*256+j
__device__ float g_bx[768];

__device__ __forceinline__ float sigm(float x) { return 1.f / (1.f + expf(-x)); }

// ---------------- pack ----------------
__global__ void k_pack(const float* __restrict__ Wi, const float* __restrict__ bi,
                       const float* __restrict__ Wv, const float* __restrict__ bv,
                       const float* __restrict__ Wr, const float* __restrict__ br,
                       const float* __restrict__ Wz, const float* __restrict__ bz,
                       const float* __restrict__ Wu, const float* __restrict__ bu)
{
    int idx = blockIdx.x * blockDim.x + threadIdx.x;
    if (idx < 512 * 1024) {
        int r = idx >> 10, k = idx & 1023;
        g_Wiv[idx] = (r < 256) ? Wi[r * 1024 + k] : Wv[(r - 256) * 1024 + k];
    }
    if (idx < 768 * 256) {
        int n = idx >> 8, k = idx & 255;
        int gate = n >> 8, jj = n & 255;
        const float* Wg = (gate == 0) ? Wr : ((gate == 1) ? Wz : Wu);
        g_Wx[idx] = Wg[jj * 512 + k];
        g_Wh[idx] = Wg[jj * 512 + 256 + k];
    }
    if (idx < 768) g_bx[idx] = (idx < 256) ? br[idx] : ((idx < 512) ? bz[idx - 256] : bu[idx - 512]);
    if (idx < 512) g_biv[idx] = (idx < 256) ? bi[idx] : bv[idx - 256];
}

// ---------------- init: raw = 0.01*mi, ss partials, usage[0] = 0 ----------------
__global__ void k_init(const float* __restrict__ mi)
{
    int row = blockIdx.x, tid = threadIdx.x;
    float v = 0.01f * mi[(size_t)row * M_ + tid];
    g_mem[(size_t)row * M_ + tid] = v;
    float ss = v * v;
    #pragma unroll
    for (int off = 16; off; off >>= 1) ss += __shfl_xor_sync(0xffffffffu, ss, off);
    __shared__ float wsum[8];
    if ((tid & 31) == 0) wsum[tid >> 5] = ss;
    __syncthreads();
    if (tid < 4) {
        int b = row >> 6, s = row & 63;
        g_ss[(b * 4 + tid) * 64 + s] = wsum[2 * tid] + wsum[2 * tid + 1];
    }
    if (tid == 0) g_usage[0][row] = 0.f;
}

// ---------------- precompute GEMMs (unchanged, passing) ----------------
template<int KTILE>
__device__ __forceinline__ void gemm_tile(const float* __restrict__ A, int lda,
                                          const float* __restrict__ W, int ldw,
                                          int K, int row0, int n0, float acc[4][4])
{
    __shared__ __align__(16) float sA[KTILE][68];
    __shared__ __align__(16) float sW[KTILE][68];
    const int tid = threadIdx.x;
    const int lr = tid >> 2, lk = (tid & 3) * 4;
    const int ty = tid >> 4, tx = tid & 15;
    for (int k0 = 0; k0 < K; k0 += KTILE) {
        float4 av = *(const float4*)(A + (size_t)(row0 + lr) * lda + k0 + lk);
        float4 wv = *(const float4*)(W + (size_t)(n0 + lr) * ldw + k0 + lk);
        __syncthreads();
        sA[lk + 0][lr] = av.x; sA[lk + 1][lr] = av.y; sA[lk + 2][lr] = av.z; sA[lk + 3][lr] = av.w;
        sW[lk + 0][lr] = wv.x; sW[lk + 1][lr] = wv.y; sW[lk + 2][lr] = wv.z; sW[lk + 3][lr] = wv.w;
        __syncthreads();
        #pragma unroll
        for (int kk = 0; kk < KTILE; kk++) {
            float4 a = *(const float4*)&sA[kk][ty * 4];
            float4 w = *(const float4*)&sW[kk][tx * 4];
            float ar[4] = {a.x, a.y, a.z, a.w};
            float wr[4] = {w.x, w.y, w.z, w.w};
            #pragma unroll
            for (int i = 0; i < 4; i++)
                #pragma unroll
                for (int j = 0; j < 4; j++)
                    acc[i][j] = fmaf(ar[i], wr[j], acc[i][j]);
        }
    }
}

__global__ void k_gemm_pre(const float* __restrict__ hidden, int mode)
{
    const float* A; const float* W; const float* bias; float* C;
    int lda, ldw, ldc, K, ntn;
    if (mode == 0) { A = hidden;     lda = 1024; W = g_Wiv; ldw = 1024; bias = g_biv; C = g_mv;    ldc = 512; K = 1024; ntn = 8;  }
    else           { A = g_mv + 256; lda = 512;  W = g_Wx;  ldw = 256;  bias = g_bx;  C = g_vproj; ldc = 768; K = 256;  ntn = 12; }
    int tr = blockIdx.x / ntn, tc = blockIdx.x % ntn;
    int row0 = tr * 64, n0 = tc * 64;
    float acc[4][4] = {};
    gemm_tile<16>(A, lda, W, ldw, K, row0, n0, acc);
    int ty = threadIdx.x >> 4, tx = threadIdx.x & 15;
    #pragma unroll
    for (int i = 0; i < 4; i++) {
        int r = row0 + ty * 4 + i;
        #pragma unroll
        for (int j = 0; j < 4; j++) {
            int n = n0 + tx * 4 + j;
            C[(size_t)r * ldc + n] = acc[i][j] + bias[n];
        }
    }
}

// ---------------- double-buffered active-row GEMM (KTILE=32, reg prefetch) ----------------
template<bool IND>
__device__ __forceinline__ void gemm_pf(const float* __restrict__ A,  // batch base [64][256] (or compressed)
                                        const float* __restrict__ W,  // g_Wh rows
                                        int n0,
                                        const int* __restrict__ sAct_,
                                        const float* __restrict__ sScl_, int cnt,
                                        float* __restrict__ sA, float* __restrict__ sWm,
                                        float acc[4][4])
{
    const int tid = threadIdx.x;
    const int lr = tid >> 2, lk = (tid & 3) * 4;   // row 0..63, col group {0,4,8,12}
    const int ty = tid >> 4, tx = tid & 15;
    const bool aval = lr < cnt;
    int arow = lr; float sc = 1.f;
    if (IND) { arow = aval ? sAct_[lr] : 0; sc = aval ? sScl_[arow] : 0.f; }
    const bool doC = (ty * 4) < cnt;
    const float* Arow = A + (size_t)arow * 256;
    const float* Wrow = W + (size_t)(n0 + lr) * 256;

    float4 a0 = make_float4(0.f,0.f,0.f,0.f), a1 = a0, w0, w1;
    if (aval) { a0 = *(const float4*)(Arow + lk); a1 = *(const float4*)(Arow + lk + 16); }
    w0 = *(const float4*)(Wrow + lk);
    w1 = *(const float4*)(Wrow + lk + 16);

    for (int kc = 0; kc < 8; kc++) {
        __syncthreads();
        {
            float4 s0 = a0, s1 = a1;
            if (IND) { s0.x*=sc; s0.y*=sc; s0.z*=sc; s0.w*=sc; s1.x*=sc; s1.y*=sc; s1.z*=sc; s1.w*=sc; }
            sA[(lk + 0) * 68 + lr] = s0.x; sA[(lk + 1) * 68 + lr] = s0.y;
            sA[(lk + 2) * 68 + lr] = s0.z; sA[(lk + 3) * 68 + lr] = s0.w;
            sA[(lk + 16) * 68 + lr] = s1.x; sA[(lk + 17) * 68 + lr] = s1.y;
            sA[(lk + 18) * 68 + lr] = s1.z; sA[(lk + 19) * 68 + lr] = s1.w;
            sWm[(lk + 0) * 68 + lr] = w0.x; sWm[(lk + 1) * 68 + lr] = w0.y;
            sWm[(lk + 2) * 68 + lr] = w0.z; sWm[(lk + 3) * 68 + lr] = w0.w;
            sWm[(lk + 16) * 68 + lr] = w1.x; sWm[(lk + 17) * 68 + lr] = w1.y;
            sWm[(lk + 18) * 68 + lr] = w1.z; sWm[(lk + 19) * 68 + lr] = w1.w;
        }
        __syncthreads();
        if (kc < 7) {   // prefetch next chunk while computing this one
            int base = (kc + 1) * 32;
            if (aval) { a0 = *(const float4*)(Arow + base + lk); a1 = *(const float4*)(Arow + base + lk + 16); }
            w0 = *(const float4*)(Wrow + base + lk);
            w1 = *(const float4*)(Wrow + base + lk + 16);
        }
        if (doC) {
            #pragma unroll
            for (int kk = 0; kk < 32; kk++) {
                float4 a = *(const float4*)&sA[kk * 68 + ty * 4];
                float4 w = *(const float4*)&sWm[kk * 68 + tx * 4];
                float ar[4] = {a.x, a.y, a.z, a.w};
                float wr[4] = {w.x, w.y, w.z, w.w};
                #pragma unroll
                for (int i = 0; i < 4; i++)
                    #pragma unroll
                    for (int j = 0; j < 4; j++)
                        acc[i][j] = fmaf(ar[i], wr[j], acc[i][j]);
            }
        }
    }
}

// ---------------- step2 (fused step1): softmax/active-list + r,z GEMM (grid 32*8) ----------------
__global__ void __launch_bounds__(256) k_step2(int t)
{
    __shared__ __align__(16) float sA[32 * 68];
    __shared__ __align__(16) float sWm[32 * 68];
    __shared__ __align__(16) float dvec[256];
    __shared__ float sScl_[64], sSco[64], sWw_[64];
    __shared__ int sAct_[64];
    __shared__ int sCnt_;

    int b = blockIdx.x >> 3, j = blockIdx.x & 7;
    int tid = threadIdx.x, lane = tid & 31, warp = tid >> 5;
    const float* usR = g_usage[t & 1];
    float*       usW = g_usage[(t + 1) & 1];

    // ---- inline step1 (redundant per block; deterministic-identical) ----
    if (tid < 64) {
        const float* ssB = g_ss + b * 256;
        float tot = ssB[tid] + ssB[64 + tid] + ssB[128 + tid] + ssB[192 + tid];
        sScl_[tid] = 1.f / fmaxf(sqrtf(tot), 1e-12f);
    }
    dvec[tid] = g_mv[(size_t)(b * T_ + t) * 512 + tid];
    __syncthreads();
    #pragma unroll
    for (int rr = 0; rr < 8; rr++) {
        int s = warp * 8 + rr;
        const float* mr = g_mem + (size_t)(b * 64 + s) * M_ + lane * 8;
        float4 m0 = *(const float4*)mr, m1 = *(const float4*)(mr + 4);
        float4 q0 = *(const float4*)&dvec[lane * 8], q1 = *(const float4*)&dvec[lane * 8 + 4];
        float p = m0.x * q0.x;
        p = fmaf(m0.y, q0.y, p); p = fmaf(m0.z, q0.z, p); p = fmaf(m0.w, q0.w, p);
        p = fmaf(m1.x, q1.x, p); p = fmaf(m1.y, q1.y, p);
        p = fmaf(m1.z, q1.z, p); p = fmaf(m1.w, q1.w, p);
        #pragma unroll
        for (int off = 16; off; off >>= 1) p += __shfl_xor_sync(0xffffffffu, p, off);
        if (lane == 0) sSco[s] = p;
    }
    __syncthreads();
    if (tid < 64) sSco[tid] = -sSco[tid] * sScl_[tid] + 0.2f * usR[b * 64 + tid];
    __syncthreads();
    if (tid < 32) {   // full warp 0: softmax
        float x0 = sSco[tid], x1 = sSco[tid + 32];
        float mx = fmaxf(x0, x1);
        #pragma unroll
        for (int off = 16; off; off >>= 1) mx = fmaxf(mx, __shfl_xor_sync(0xffffffffu, mx, off));
        float e0 = expf(x0 - mx), e1 = expf(x1 - mx);
        float ssum = e0 + e1;
        #pragma unroll
        for (int off = 16; off; off >>= 1) ssum += __shfl_xor_sync(0xffffffffu, ssum, off);
        float inv = 1.f / ssum;
        sWw_[tid] = e0 * inv; sWw_[tid + 32] = e1 * inv;
    }
    __syncthreads();
    if (tid < 32) {   // full warp 0: active list
        bool a0 = sWw_[tid] > 0.01f, a1 = sWw_[tid + 32] > 0.01f;
        unsigned m0 = __ballot_sync(0xffffffffu, a0);
        unsigned m1 = __ballot_sync(0xffffffffu, a1);
        int c0 = __popc(m0);
        if (a0) sAct_[__popc(m0 & ((1u << tid) - 1))] = tid;
        if (a1) sAct_[c0 + __popc(m1 & ((1u << tid) - 1))] = tid + 32;
        if (tid == 0) sCnt_ = c0 + __popc(m1);
    }
    __syncthreads();
    const int cnt = sCnt_;
    // publish for step3 + usage state (single writer: block j==0)
    if (j == 0 && tid < 64) {
        float w_ = sWw_[tid];
        g_ww[b * 64 + tid] = w_;
        g_scl[b * 64 + tid] = sScl_[tid];
        usW[b * 64 + tid] = (usR[b * 64 + tid] + (w_ > 0.01f ? w_ : 0.f)) * 0.99f;
        if (tid < cnt) g_act[b * 64 + tid] = sAct_[tid];
        if (tid == 0) g_cnt[b] = cnt;
    }

    // ---- r,z GEMM over active rows ----
    float acc[4][4] = {};
    gemm_pf<true>(g_mem + (size_t)b * S_ * M_, g_Wh, j * 64, sAct_, sScl_, cnt, sA, sWm, acc);

    int ty = tid >> 4, tx = tid & 15;
    float4 vp = __ldcg((const float4*)(g_vproj + (size_t)(b * T_ + t) * 768 + j * 64 + tx * 4));
    float vv[4] = {vp.x, vp.y, vp.z, vp.w};
    #pragma unroll
    for (int i = 0; i < 4; i++) {
        int arow = ty * 4 + i;
        if (arow >= cnt) continue;     // no sync primitives below
        int row = sAct_[arow];
        float4 o; float* op = (float*)&o;
        if (j < 4) {                    // r gate -> r * mem_norm
            float sc = sScl_[row];
            float4 m4 = __ldcg((const float4*)(g_mem + (size_t)(b * 64 + row) * 256 + j * 64 + tx * 4));
            float mm[4] = {m4.x * sc, m4.y * sc, m4.z * sc, m4.w * sc};
            #pragma unroll
            for (int q = 0; q < 4; q++) op[q] = sigm(acc[i][q] + vv[q]) * mm[q];
            __stcg((float4*)(g_rm + (size_t)(b * 64 + arow) * 256 + j * 64 + tx * 4), o);
        } else {                        // z gate
            #pragma unroll
            for (int q = 0; q < 4; q++) op[q] = sigm(acc[i][q] + vv[q]);
            __stcg((float4*)(g_zg + (size_t)(b * 64 + arow) * 256 + (j - 4) * 64 + tx * 4), o);
        }
    }
}

// ---------------- step3: cand GEMM + blend in place + ss partials (grid 32*4) ----------------
__global__ void __launch_bounds__(256) k_step3(int t)
{
    __shared__ __align__(16) float sA[32 * 68];
    __shared__ __align__(16) float sWm[32 * 68];
    __shared__ int sAct_[64]; __shared__ float sScl_[64]; __shared__ int sCnt_;
    int b = blockIdx.x >> 2, j = blockIdx.x & 3;
    int tid = threadIdx.x;
    if (tid < 64) { sAct_[tid] = g_act[b * 64 + tid]; sScl_[tid] = g_scl[b * 64 + tid]; }
    if (tid == 0) sCnt_ = g_cnt[b];
    __syncthreads();
    const int cnt = sCnt_;

    float acc[4][4] = {};
    gemm_pf<false>(g_rm + (size_t)b * S_ * M_, g_Wh, 512 + j * 64, sAct_, sScl_, cnt, sA, sWm, acc);

    int ty = tid >> 4, tx = tid & 15;
    float4 vp = __ldcg((const float4*)(g_vproj + (size_t)(b * T_ + t) * 768 + 512 + j * 64 + tx * 4));
    float vv[4] = {vp.x, vp.y, vp.z, vp.w};
    #pragma unroll
    for (int i = 0; i < 4; i++) {
        int arow = ty * 4 + i;
        bool ok = arow < cnt;
        int row = ok ? sAct_[arow] : 0;
        float ssum = 0.f;
        if (ok) {
            float sc = sScl_[row];
            float w_ = g_ww[b * 64 + row] * 0.5f;
            float4 z4 = __ldcg((const float4*)(g_zg + (size_t)(b * 64 + arow) * 256 + j * 64 + tx * 4));
            float4 m4 = __ldcg((const float4*)(g_mem + (size_t)(b * 64 + row) * 256 + j * 64 + tx * 4));
            float zz[4] = {z4.x, z4.y, z4.z, z4.w};
            float mm[4] = {m4.x * sc, m4.y * sc, m4.z * sc, m4.w * sc};
            float4 o; float* op = (float*)&o;
            #pragma unroll
            for (int q = 0; q < 4; q++) {
                float cand = tanhf(acc[i][q] + vv[q]);
                float nh = (1.f - zz[q]) * mm[q] + zz[q] * cand;
                float ov = mm[q] * (1.f - w_) + nh * w_;
                op[q] = ov; ssum = fmaf(ov, ov, ssum);
            }
            __stcg((float4*)(g_mem + (size_t)(b * 64 + row) * 256 + j * 64 + tx * 4), o);
        }
        // UNCONDITIONAL shuffles; xor<=8 keeps the two 16-lane tx groups independent
        ssum += __shfl_xor_sync(0xffffffffu, ssum, 1);
        ssum += __shfl_xor_sync(0xffffffffu, ssum, 2);
        ssum += __shfl_xor_sync(0xffffffffu, ssum, 4);
        ssum += __shfl_xor_sync(0xffffffffu, ssum, 8);
        if (ok && tx == 0) g_ss[(b * 4 + j) * 64 + row] = ssum;
    }
}

// ---------------- final normalize into d_out ----------------
__global__ void k_fin(float* __restrict__ out)
{
    int row = blockIdx.x, tid = threadIdx.x;
    __shared__ float sc;
    if (tid == 0) {
        int b = row >> 6, s = row & 63;
        const float* ssB = g_ss + b * 256;
        float tot = ssB[s] + ssB[64 + s] + ssB[128 + s] + ssB[192 + s];
        sc = 1.f / fmaxf(sqrtf(tot), 1e-12f);
    }
    __syncthreads();
    out[(size_t)row * M_ + tid] = g_mem[(size_t)row * M_ + tid] * sc;
}

// ---------------- launch ----------------
extern "C" void kernel_launch(void* const* d_in, const int* in_sizes, int n_in,
                              void* d_out, int out_size)
{
    const float* hidden  = (const float*)d_in[0];
    const float* meminit = (const float*)d_in[1];
    const float* Wi = (const float*)d_in[2];
    const float* bi = (const float*)d_in[3];
    const float* Wv = (const float*)d_in[4];
    const float* bv = (const float*)d_in[5];
    const float* Wr = (const float*)d_in[6];
    const float* br = (const float*)d_in[7];
    const float* Wz = (const float*)d_in[8];
    const float* bz = (const float*)d_in[9];
    const float* Wu = (const float*)d_in[10];
    const float* bu = (const float*)d_in[11];

    k_pack<<<2048, 256>>>(Wi, bi, Wv, bv, Wr, br, Wz, bz, Wu, bu);
    k_init<<<ROWS_, 256>>>(meminit);
    k_gemm_pre<<<128 * 8, 256>>>(hidden, 0);    // mem_input | vals
    k_gemm_pre<<<128 * 12, 256>>>(hidden, 1);   // VR | VZ | VU

    for (int t = 0; t < T_; t++) {
        k_step2<<<B_ * 8, 256>>>(t);
        k_step3<<<B_ * 4, 256>>>(t);
    }
    k_fin<<<ROWS_, 256>>>((float*)d_out);
}